// round 5
// baseline (speedup 1.0000x reference)
#include <cuda_runtime.h>
#include <math.h>

#define KCODES 1024
#define DDIM   64

// -------- scratch (device globals; no allocation allowed) --------
__device__ float g_en2[KCODES];
__device__ float g_nrm[KCODES * DDIM];
__device__ int   g_hist[KCODES];
__device__ float g_usedp[4];
__device__ float g_pcommit[1024];
__device__ float g_pent[1024];
__device__ float g_gram[4096];

// -------- codebook prep: ||e||^2, normalized+masked rows, zero hist/gram, used partials --------
__global__ void prep_kernel(const float* __restrict__ emb, const float* __restrict__ cc) {
    int row = blockIdx.x * blockDim.x + threadIdx.x;   // 0..1023
    const float4* e4 = ((const float4*)emb) + (size_t)row * (DDIM / 4);
    float4 v[16];
    float s = 0.f;
#pragma unroll
    for (int i = 0; i < 16; i++) {
        v[i] = e4[i];
        s += v[i].x * v[i].x + v[i].y * v[i].y + v[i].z * v[i].z + v[i].w * v[i].w;
    }
    g_en2[row] = s;
    g_hist[row] = 0;
#pragma unroll
    for (int i = 0; i < 4; i++) g_gram[row * 4 + i] = 0.f;
    float nr = fmaxf(sqrtf(s), 1e-12f);
    float msk = (cc[row] >= 1.f) ? 1.f : 0.f;
    float sc = msk / nr;
    float4* o4 = ((float4*)g_nrm) + (size_t)row * (DDIM / 4);
#pragma unroll
    for (int i = 0; i < 16; i++) {
        float4 t = v[i];
        t.x *= sc; t.y *= sc; t.z *= sc; t.w *= sc;
        o4[i] = t;
    }
    __shared__ float sh[256];
    sh[threadIdx.x] = msk;
    __syncthreads();
    for (int st = 128; st > 0; st >>= 1) {
        if (threadIdx.x < st) sh[threadIdx.x] += sh[threadIdx.x + st];
        __syncthreads();
    }
    if (threadIdx.x == 0) g_usedp[blockIdx.x] = sh[0];
}

// -------- ortho partial Gram: block b covers codes [b*64, b*64+64), accumulates into g_gram --------
__global__ __launch_bounds__(256, 4)
void ortho_kernel() {
    __shared__ float nt[64 * 68];
    int tid = threadIdx.x;
    int k0 = blockIdx.x * 64;
#pragma unroll
    for (int i = 0; i < 16; i++) {
        int v = tid + 256 * i;
        int k = v >> 6, d = v & 63;
        nt[k * 68 + d] = g_nrm[(size_t)(k0 + k) * DDIM + d];
    }
    __syncthreads();
    int a = tid >> 2;          // 0..63
    int bg = tid & 3;          // 0..3 -> cols bg*16..+15
    float acc[16];
#pragma unroll
    for (int i = 0; i < 16; i++) acc[i] = 0.f;
#pragma unroll 4
    for (int k = 0; k < 64; k++) {
        float va = nt[k * 68 + a];
        const float4* bp = (const float4*)(nt + k * 68 + bg * 16);
        float4 q0 = bp[0], q1 = bp[1], q2 = bp[2], q3 = bp[3];
        acc[0]  = fmaf(va, q0.x, acc[0]);  acc[1]  = fmaf(va, q0.y, acc[1]);
        acc[2]  = fmaf(va, q0.z, acc[2]);  acc[3]  = fmaf(va, q0.w, acc[3]);
        acc[4]  = fmaf(va, q1.x, acc[4]);  acc[5]  = fmaf(va, q1.y, acc[5]);
        acc[6]  = fmaf(va, q1.z, acc[6]);  acc[7]  = fmaf(va, q1.w, acc[7]);
        acc[8]  = fmaf(va, q2.x, acc[8]);  acc[9]  = fmaf(va, q2.y, acc[9]);
        acc[10] = fmaf(va, q2.z, acc[10]); acc[11] = fmaf(va, q2.w, acc[11]);
        acc[12] = fmaf(va, q3.x, acc[12]); acc[13] = fmaf(va, q3.y, acc[13]);
        acc[14] = fmaf(va, q3.z, acc[14]); acc[15] = fmaf(va, q3.w, acc[15]);
    }
    float* op = g_gram + a * 64 + bg * 16;
#pragma unroll
    for (int i = 0; i < 16; i++) atomicAdd(op + i, acc[i]);
}

// -------- main kernel: 32-row x 1024-code tiles, 1024 blocks, 3 CTAs/SM --------
// smem floats: Xs [64][36] = 2304 | Es [64][132] = 8448 | en2s 128  -> 10880 floats = 43520 B
// overlays (post-mainloop): Rm@0 Rz@512 Rs@1024 Ri@1536 (over Xs); idxRow@2304 scr@2368 (over Es)
#define SMEM_FLOATS 10880
#define SMEM_BYTES  (SMEM_FLOATS * 4)

__global__ __launch_bounds__(256, 3)
void main_kernel(const float* __restrict__ x, const float* __restrict__ emb,
                 float* __restrict__ qout, float* __restrict__ idxout) {
    extern __shared__ float sm[];
    float* Xs   = sm;               // [64 d][36] (32 rows + pad)
    float* Es   = sm + 2304;        // [64 d][132] (128 codes + pad)
    float* en2s = sm + 10752;       // [128]
    float* Rm   = sm;               // overlays Xs after mainloop
    float* Rz   = sm + 512;
    float* Rs   = sm + 1024;
    int*   Ri   = (int*)(sm + 1536);
    int*   idxRow = (int*)(sm + 2304);  // overlays Es
    float* scr  = sm + 2368;            // [256], overlays Es

    const int tid = threadIdx.x;
    const int tx = tid & 15;   // code group (8 codes)
    const int ty = tid >> 4;   // row pair (rows ty*2, ty*2+1)
    const int r0 = blockIdx.x * 32;

    // load X tile transposed: Xs[d][row], 512 float4s
#pragma unroll
    for (int i = 0; i < 2; i++) {
        int v = tid + 256 * i;
        int row = v >> 4;
        int c4 = v & 15;
        float4 t = ((const float4*)x)[(size_t)(r0 + row) * 16 + c4];
        int d = c4 * 4;
        Xs[(d + 0) * 36 + row] = t.x;
        Xs[(d + 1) * 36 + row] = t.y;
        Xs[(d + 2) * 36 + row] = t.z;
        Xs[(d + 3) * 36 + row] = t.w;
    }

    float m[2], Z[2], S[2];
    int   bi[2];
#pragma unroll
    for (int i = 0; i < 2; i++) { m[i] = -1e30f; Z[i] = 0.f; S[i] = 0.f; bi[i] = 0; }

    for (int t = 0; t < 8; t++) {
        __syncthreads();
        // load E tile transposed: Es[d][code], 2048 float4s
#pragma unroll
        for (int i = 0; i < 8; i++) {
            int v = tid + 256 * i;
            int code = v >> 4;
            int c4 = v & 15;
            float4 tv = ((const float4*)emb)[(size_t)(t * 128 + code) * 16 + c4];
            int d = c4 * 4;
            Es[(d + 0) * 132 + code] = tv.x;
            Es[(d + 1) * 132 + code] = tv.y;
            Es[(d + 2) * 132 + code] = tv.z;
            Es[(d + 3) * 132 + code] = tv.w;
        }
        if (tid < 128) en2s[tid] = g_en2[t * 128 + tid];
        __syncthreads();

        float acc[2][8];
#pragma unroll
        for (int i = 0; i < 2; i++)
#pragma unroll
            for (int j = 0; j < 8; j++) acc[i][j] = 0.f;

#pragma unroll 8
        for (int kk = 0; kk < 64; kk++) {
            float2 a2 = *(const float2*)(Xs + kk * 36 + ty * 2);
            float4 b0 = *(const float4*)(Es + kk * 132 + tx * 8);
            float4 b1 = *(const float4*)(Es + kk * 132 + tx * 8 + 4);
            float b[8] = { b0.x, b0.y, b0.z, b0.w, b1.x, b1.y, b1.z, b1.w };
#pragma unroll
            for (int j = 0; j < 8; j++) {
                acc[0][j] = fmaf(a2.x, b[j], acc[0][j]);
                acc[1][j] = fmaf(a2.y, b[j], acc[1][j]);
            }
        }

        // fused epilogue: a' = 2*dot - ||e||^2 (softmax/argmin invariant to ||x||^2)
#pragma unroll
        for (int j = 0; j < 8; j++) {
            float e2 = en2s[tx * 8 + j];
            int jg = t * 128 + tx * 8 + j;
#pragma unroll
            for (int i = 0; i < 2; i++) {
                float av = fmaf(2.f, acc[i][j], -e2);
                if (av > m[i]) {
                    float scl = __expf(m[i] - av);
                    Z[i] = fmaf(Z[i], scl, 1.f);
                    S[i] = fmaf(S[i], scl, av);
                    m[i] = av; bi[i] = jg;
                } else {
                    float p = __expf(av - m[i]);
                    Z[i] += p;
                    S[i] = fmaf(av, p, S[i]);
                }
            }
        }
    }

    __syncthreads();   // Xs/Es dead -> overlays become valid
#pragma unroll
    for (int i = 0; i < 2; i++) {
        int row = ty * 2 + i;
        Rm[row * 16 + tx] = m[i];
        Rz[row * 16 + tx] = Z[i];
        Rs[row * 16 + tx] = S[i];
        Ri[row * 16 + tx] = bi[i];
    }
    __syncthreads();

    float H = 0.f;
    if (tid < 32) {
        int row = tid;
        float mm = -1e30f;
        int ii = 0x7fffffff;
#pragma unroll
        for (int t2 = 0; t2 < 16; t2++) {
            float mv = Rm[row * 16 + t2];
            int iv = Ri[row * 16 + t2];
            if (mv > mm) { mm = mv; ii = iv; }
            else if (mv == mm && iv < ii) ii = iv;
        }
        float zz = 0.f, ss = 0.f;
#pragma unroll
        for (int t2 = 0; t2 < 16; t2++) {
            float scl = __expf(Rm[row * 16 + t2] - mm);
            zz = fmaf(Rz[row * 16 + t2], scl, zz);
            ss = fmaf(Rs[row * 16 + t2], scl, ss);
        }
        H = mm + __logf(zz) - ss / zz;
        idxRow[row] = ii;
        idxout[r0 + row] = (float)ii;
        atomicAdd(&g_hist[ii], 1);
    }
    scr[tid] = (tid < 32) ? H : 0.f;
    __syncthreads();
    for (int s = 128; s > 0; s >>= 1) {
        if (tid < s) scr[tid] += scr[tid + s];
        __syncthreads();
    }
    if (tid == 0) g_pent[blockIdx.x] = scr[0];
    __syncthreads();

    // gather quantized rows, write output, accumulate commitment (512 float4s)
    float ca = 0.f;
#pragma unroll
    for (int i = 0; i < 2; i++) {
        int v = tid + 256 * i;
        int row = v >> 4;
        int c4 = v & 15;
        int code = idxRow[row];
        float4 q = ((const float4*)emb)[(size_t)code * 16 + c4];
        float4 xv = ((const float4*)x)[(size_t)(r0 + row) * 16 + c4];
        ((float4*)qout)[(size_t)(r0 + row) * 16 + c4] = q;
        float dx = q.x - xv.x, dy = q.y - xv.y, dz = q.z - xv.z, dw = q.w - xv.w;
        ca += dx * dx + dy * dy + dz * dz + dw * dw;
    }
    __syncthreads();
    scr[tid] = ca;
    __syncthreads();
    for (int s = 128; s > 0; s >>= 1) {
        if (tid < s) scr[tid] += scr[tid + s];
        __syncthreads();
    }
    if (tid == 0) g_pcommit[blockIdx.x] = scr[0];
}

// -------- finalize scalars --------
__global__ void fin_kernel(float* __restrict__ out, int N, int nblocks) {
    __shared__ float sh[256];
    int tid = threadIdx.x;

    float v = 0.f;
    for (int i = tid; i < nblocks; i += 256) v += g_pcommit[i];
    sh[tid] = v;
    __syncthreads();
    for (int s = 128; s > 0; s >>= 1) { if (tid < s) sh[tid] += sh[tid + s]; __syncthreads(); }
    float commitSum = sh[0];
    __syncthreads();

    v = 0.f;
    for (int i = tid; i < nblocks; i += 256) v += g_pent[i];
    sh[tid] = v;
    __syncthreads();
    for (int s = 128; s > 0; s >>= 1) { if (tid < s) sh[tid] += sh[tid + s]; __syncthreads(); }
    float entSum = sh[0];
    __syncthreads();

    // ortho: sum of squared Gram entries (already fully accumulated)
    v = 0.f;
    for (int e = tid; e < 4096; e += 256) {
        float g = g_gram[e];
        v = fmaf(g, g, v);
    }
    sh[tid] = v;
    __syncthreads();
    for (int s = 128; s > 0; s >>= 1) { if (tid < s) sh[tid] += sh[tid + s]; __syncthreads(); }
    float orthoSum = sh[0];
    __syncthreads();

    v = 0.f;
    for (int i = tid; i < KCODES; i += 256) {
        float avg = (float)g_hist[i] / (float)N;
        v += avg * logf(avg + 1e-10f);
    }
    sh[tid] = v;
    __syncthreads();
    for (int s = 128; s > 0; s >>= 1) { if (tid < s) sh[tid] += sh[tid + s]; __syncthreads(); }
    float psum = sh[0];

    if (tid == 0) {
        size_t Q = (size_t)N * DDIM;
        float nu = g_usedp[0] + g_usedp[1] + g_usedp[2] + g_usedp[3];
        out[Q + 0] = commitSum / (float)Q;                 // commitment_loss
        out[Q + 1] = orthoSum / (nu * nu) - 1.f / nu;      // ortho_loss
        out[Q + 2] = entSum / ((float)N * 10.f);           // entropy_loss (/log2(1024))
        out[Q + 3] = expf(-psum);                          // perplexity
        out[Q + 4] = nu / (float)KCODES;                   // coverage
    }
}

extern "C" void kernel_launch(void* const* d_in, const int* in_sizes, int n_in,
                              void* d_out, int out_size) {
    const float* x   = (const float*)d_in[0];   // [16,2048,64] fp32
    const float* emb = (const float*)d_in[1];   // [1024,64] fp32
    const float* cc  = (const float*)d_in[2];   // [1024] fp32
    int N = in_sizes[0] / DDIM;                 // 32768 rows
    int nblocks = N / 32;                       // 1024

    float* out = (float*)d_out;
    float* qout = out;                                  // [N*64]
    float* idxout = out + (size_t)N * DDIM + 5;         // [N] after 5 scalars

    cudaFuncSetAttribute(main_kernel, cudaFuncAttributeMaxDynamicSharedMemorySize, SMEM_BYTES);

    prep_kernel<<<4, 256>>>(emb, cc);
    ortho_kernel<<<16, 256>>>();
    main_kernel<<<nblocks, 256, SMEM_BYTES>>>(x, emb, qout, idxout);
    fin_kernel<<<1, 256>>>(out, N, nblocks);
}

// round 8
// speedup vs baseline: 2.6664x; 2.6664x over previous
#include <cuda_runtime.h>
#include <math.h>
#include <stdint.h>

#define KCODES 1024
#define DDIM   64
#define NBLOCKS 256       // 32768 rows / 128 rows per block
#define CTILES  16        // 1024 codes / 64 codes per tile

// ---------------- device scratch (no allocation allowed) ----------------
__device__ float g_en2[KCODES];
__device__ float g_nrm[KCODES * DDIM];
__device__ int   g_hist[KCODES];
__device__ float g_usedp[4];
__device__ float g_pcommit[NBLOCKS];
__device__ float g_pent[NBLOCKS];
__device__ float g_gram[4096];
__device__ int   g_done;

// ---------------- helpers ----------------
__device__ __forceinline__ float to_tf32(float v) {
    float r;
    asm("cvt.rna.tf32.f32 %0, %1;" : "=f"(r) : "f"(v));
    return r;
}

// D += A(row-major m16k8, tf32) * B(col-major k8n8, tf32), fp32 accum
__device__ __forceinline__ void mma_tf32(float& d0, float& d1, float& d2, float& d3,
                                         const uint32_t a[4], uint32_t b0, uint32_t b1) {
    asm("mma.sync.aligned.m16n8k8.row.col.f32.tf32.tf32.f32 "
        "{%0,%1,%2,%3}, {%4,%5,%6,%7}, {%8,%9}, {%0,%1,%2,%3};"
        : "+f"(d0), "+f"(d1), "+f"(d2), "+f"(d3)
        : "r"(a[0]), "r"(a[1]), "r"(a[2]), "r"(a[3]), "r"(b0), "r"(b1));
}

// proven online-softmax update
#define UPDATE(mv, Zv, Sv, biv, av, jg) do {                                  \
    float _av = (av);                                                         \
    if (_av > (mv)) {                                                         \
        float _scl = __expf((mv) - _av);                                      \
        (Zv) = fmaf((Zv), _scl, 1.f);                                         \
        (Sv) = fmaf((Sv), _scl, _av);                                         \
        (mv) = _av; (biv) = (jg);                                             \
    } else {                                                                  \
        float _p = __expf(_av - (mv));                                        \
        (Zv) += _p;                                                           \
        (Sv) = fmaf(_av, _p, (Sv));                                           \
    } } while (0)

#define MERGE(mv, Zv, Sv, biv, m2, Z2, S2, b2) do {                           \
    float _mm = fmaxf((mv), (m2));                                            \
    float _sA = __expf((mv) - _mm);                                           \
    float _sB = __expf((m2) - _mm);                                           \
    float _Zn = (Zv) * _sA + (Z2) * _sB;                                      \
    float _Sn = (Sv) * _sA + (S2) * _sB;                                      \
    if ((m2) > (mv) || ((m2) == (mv) && (b2) < (biv))) (biv) = (b2);          \
    (mv) = _mm; (Zv) = _Zn; (Sv) = _Sn; } while (0)

// ---------------- prep: norms, normalized+masked rows, zero hist/gram/done, used ----------------
__global__ void prep_kernel(const float* __restrict__ emb, const float* __restrict__ cc) {
    int row = blockIdx.x * blockDim.x + threadIdx.x;   // 0..1023
    const float4* e4 = ((const float4*)emb) + (size_t)row * 16;
    float4 v[16];
    float s = 0.f;
#pragma unroll
    for (int i = 0; i < 16; i++) {
        v[i] = e4[i];
        s += v[i].x * v[i].x + v[i].y * v[i].y + v[i].z * v[i].z + v[i].w * v[i].w;
    }
    g_en2[row] = s;
    g_hist[row] = 0;
#pragma unroll
    for (int i = 0; i < 4; i++) g_gram[row * 4 + i] = 0.f;
    if (row == 0) g_done = 0;

    float nr = fmaxf(sqrtf(s), 1e-12f);
    float msk = (cc[row] >= 1.f) ? 1.f : 0.f;
    float sc = msk / nr;
    float4* o4 = ((float4*)g_nrm) + (size_t)row * 16;
#pragma unroll
    for (int i = 0; i < 16; i++) {
        float4 t = v[i];
        t.x *= sc; t.y *= sc; t.z *= sc; t.w *= sc;
        o4[i] = t;
    }
    __shared__ float sh[256];
    sh[threadIdx.x] = msk;
    __syncthreads();
    for (int st = 128; st > 0; st >>= 1) {
        if (threadIdx.x < st) sh[threadIdx.x] += sh[threadIdx.x + st];
        __syncthreads();
    }
    if (threadIdx.x == 0) g_usedp[blockIdx.x] = sh[0];
}

// ---------------- ortho partial Gram (proven) ----------------
__global__ __launch_bounds__(256, 4)
void ortho_kernel() {
    __shared__ float nt[64 * 68];
    int tid = threadIdx.x;
    int k0 = blockIdx.x * 64;
#pragma unroll
    for (int i = 0; i < 16; i++) {
        int v = tid + 256 * i;
        int k = v >> 6, d = v & 63;
        nt[k * 68 + d] = g_nrm[(size_t)(k0 + k) * DDIM + d];
    }
    __syncthreads();
    int a = tid >> 2;
    int bg = tid & 3;
    float acc[16];
#pragma unroll
    for (int i = 0; i < 16; i++) acc[i] = 0.f;
#pragma unroll 4
    for (int k = 0; k < 64; k++) {
        float va = nt[k * 68 + a];
        const float4* bp = (const float4*)(nt + k * 68 + bg * 16);
        float4 q0 = bp[0], q1 = bp[1], q2 = bp[2], q3 = bp[3];
        acc[0]  = fmaf(va, q0.x, acc[0]);  acc[1]  = fmaf(va, q0.y, acc[1]);
        acc[2]  = fmaf(va, q0.z, acc[2]);  acc[3]  = fmaf(va, q0.w, acc[3]);
        acc[4]  = fmaf(va, q1.x, acc[4]);  acc[5]  = fmaf(va, q1.y, acc[5]);
        acc[6]  = fmaf(va, q1.z, acc[6]);  acc[7]  = fmaf(va, q1.w, acc[7]);
        acc[8]  = fmaf(va, q2.x, acc[8]);  acc[9]  = fmaf(va, q2.y, acc[9]);
        acc[10] = fmaf(va, q2.z, acc[10]); acc[11] = fmaf(va, q2.w, acc[11]);
        acc[12] = fmaf(va, q3.x, acc[12]); acc[13] = fmaf(va, q3.y, acc[13]);
        acc[14] = fmaf(va, q3.z, acc[14]); acc[15] = fmaf(va, q3.w, acc[15]);
    }
    float* op = g_gram + a * 64 + bg * 16;
#pragma unroll
    for (int i = 0; i < 16; i++) atomicAdd(op + i, acc[i]);
}

// ---------------- main: mma.sync tf32 3-term split GEMM + fused softmax/argmax ----------------
__global__ __launch_bounds__(256, 2)
void main_kernel(const float* __restrict__ x, const float* __restrict__ emb,
                 float* __restrict__ out, int N) {
    __shared__ float Es_hi[64 * 68];   // [code][k], pad 68
    __shared__ float Es_lo[64 * 68];
    __shared__ float en2s[64];
    __shared__ float Rm[128], Rz[128], Rs[128];
    __shared__ int   RiA[128], idxRow[128];
    __shared__ float scr[256];
    __shared__ int   flg;

    const int tid  = threadIdx.x;
    const int warp = tid >> 5;
    const int lane = tid & 31;
    const int gid  = lane >> 2;   // 0..7
    const int t4   = lane & 3;    // 0..3
    const int r0   = blockIdx.x * 128;

    float* qout   = out;
    float* idxout = out + (size_t)N * DDIM + 5;

    // ---- load A fragments once: rows warp*16+gid (+8), tf32 hi/lo ----
    uint32_t a_hi[8][4], a_lo[8][4];
    {
        const float* p0 = x + (size_t)(r0 + warp * 16 + gid) * DDIM + t4;
        const float* p1 = p0 + 8 * DDIM;
#pragma unroll
        for (int kk = 0; kk < 8; kk++) {
            float xv[4] = { p0[kk * 8], p1[kk * 8], p0[kk * 8 + 4], p1[kk * 8 + 4] };
#pragma unroll
            for (int e = 0; e < 4; e++) {
                float hi = to_tf32(xv[e]);
                a_hi[kk][e] = __float_as_uint(hi);
                a_lo[kk][e] = __float_as_uint(to_tf32(xv[e] - hi));
            }
        }
    }

    float m0 = -1e30f, Z0 = 0.f, S0 = 0.f;
    float m1 = -1e30f, Z1 = 0.f, S1 = 0.f;
    int   b0i = 0, b1i = 0;

    // prefetch tile 0 (4 float4 per thread = one 64x64 tile per 256 threads)
    float4 pre[4];
#pragma unroll
    for (int i = 0; i < 4; i++) {
        int v = tid + 256 * i;
        pre[i] = ((const float4*)emb)[(size_t)(v >> 4) * 16 + (v & 15)];
    }

    for (int t = 0; t < CTILES; t++) {
        __syncthreads();
        // convert + store tile t into smem (tf32 hi/lo)
#pragma unroll
        for (int i = 0; i < 4; i++) {
            int v = tid + 256 * i;
            int code = v >> 4, c4 = v & 15;
            float4 tv = pre[i];
            float4 h, l;
            h.x = to_tf32(tv.x); l.x = to_tf32(tv.x - h.x);
            h.y = to_tf32(tv.y); l.y = to_tf32(tv.y - h.y);
            h.z = to_tf32(tv.z); l.z = to_tf32(tv.z - h.z);
            h.w = to_tf32(tv.w); l.w = to_tf32(tv.w - h.w);
            *(float4*)(Es_hi + code * 68 + c4 * 4) = h;
            *(float4*)(Es_lo + code * 68 + c4 * 4) = l;
        }
        if (tid < 64) en2s[tid] = g_en2[t * 64 + tid];
        __syncthreads();
        // prefetch tile t+1 (overlaps MMA)
        if (t + 1 < CTILES) {
#pragma unroll
            for (int i = 0; i < 4; i++) {
                int v = tid + 256 * i;
                pre[i] = ((const float4*)emb)[(size_t)((t + 1) * 64 + (v >> 4)) * 16 + (v & 15)];
            }
        }

        // 8 n-tiles of 8 codes each
#pragma unroll
        for (int ntl = 0; ntl < 8; ntl++) {
            float d0 = 0.f, d1 = 0.f, d2 = 0.f, d3 = 0.f;
            const float* bh = Es_hi + (ntl * 8 + gid) * 68 + t4;
            const float* bl = Es_lo + (ntl * 8 + gid) * 68 + t4;
#pragma unroll
            for (int kk = 0; kk < 8; kk++) {
                uint32_t bh0 = __float_as_uint(bh[kk * 8]);
                uint32_t bh1 = __float_as_uint(bh[kk * 8 + 4]);
                uint32_t bl0 = __float_as_uint(bl[kk * 8]);
                uint32_t bl1 = __float_as_uint(bl[kk * 8 + 4]);
                mma_tf32(d0, d1, d2, d3, a_hi[kk], bh0, bh1);
                mma_tf32(d0, d1, d2, d3, a_hi[kk], bl0, bl1);
                mma_tf32(d0, d1, d2, d3, a_lo[kk], bh0, bh1);
            }
            // epilogue: logit = 2*dot - ||e||^2; online softmax + argmax
            int col0 = t * 64 + ntl * 8 + 2 * t4;
            float e20 = en2s[ntl * 8 + 2 * t4];
            float e21 = en2s[ntl * 8 + 2 * t4 + 1];
            UPDATE(m0, Z0, S0, b0i, fmaf(2.f, d0, -e20), col0);
            UPDATE(m0, Z0, S0, b0i, fmaf(2.f, d1, -e21), col0 + 1);
            UPDATE(m1, Z1, S1, b1i, fmaf(2.f, d2, -e20), col0);
            UPDATE(m1, Z1, S1, b1i, fmaf(2.f, d3, -e21), col0 + 1);
        }
    }

    // ---- merge the 4 column-threads of each row (shfl within quad) ----
#pragma unroll
    for (int off = 1; off <= 2; off <<= 1) {
        float m2 = __shfl_xor_sync(0xffffffffu, m0, off);
        float Z2 = __shfl_xor_sync(0xffffffffu, Z0, off);
        float S2 = __shfl_xor_sync(0xffffffffu, S0, off);
        int   b2 = __shfl_xor_sync(0xffffffffu, b0i, off);
        MERGE(m0, Z0, S0, b0i, m2, Z2, S2, b2);
        float m3 = __shfl_xor_sync(0xffffffffu, m1, off);
        float Z3 = __shfl_xor_sync(0xffffffffu, Z1, off);
        float S3 = __shfl_xor_sync(0xffffffffu, S1, off);
        int   b3 = __shfl_xor_sync(0xffffffffu, b1i, off);
        MERGE(m1, Z1, S1, b1i, m3, Z3, S3, b3);
    }
    if (t4 == 0) {
        int rowA = warp * 16 + gid;
        Rm[rowA] = m0; Rz[rowA] = Z0; Rs[rowA] = S0; RiA[rowA] = b0i;
        Rm[rowA + 8] = m1; Rz[rowA + 8] = Z1; Rs[rowA + 8] = S1; RiA[rowA + 8] = b1i;
    }
    __syncthreads();

    // ---- per-row entropy + index ----
    float H = 0.f;
    if (tid < 128) {
        float mm = Rm[tid], zz = Rz[tid], ss = Rs[tid];
        int ii = RiA[tid];
        H = mm + __logf(zz) - ss / zz;
        idxRow[tid] = ii;
        idxout[r0 + tid] = (float)ii;
        atomicAdd(&g_hist[ii], 1);
    }
    scr[tid] = (tid < 128) ? H : 0.f;
    __syncthreads();
    for (int s = 128; s > 0; s >>= 1) {
        if (tid < s) scr[tid] += scr[tid + s];
        __syncthreads();
    }
    if (tid == 0) g_pent[blockIdx.x] = scr[0];
    __syncthreads();

    // ---- gather quantized rows + commitment ----
    float ca = 0.f;
#pragma unroll
    for (int i = 0; i < 8; i++) {
        int v = tid + 256 * i;
        int row = v >> 4;
        int c4 = v & 15;
        int code = idxRow[row];
        float4 q  = ((const float4*)emb)[(size_t)code * 16 + c4];
        float4 xv = ((const float4*)x)[(size_t)(r0 + row) * 16 + c4];
        ((float4*)qout)[(size_t)(r0 + row) * 16 + c4] = q;
        float dx = q.x - xv.x, dy = q.y - xv.y, dz = q.z - xv.z, dw = q.w - xv.w;
        ca += dx * dx + dy * dy + dz * dz + dw * dw;
    }
    __syncthreads();
    scr[tid] = ca;
    __syncthreads();
    for (int s = 128; s > 0; s >>= 1) {
        if (tid < s) scr[tid] += scr[tid + s];
        __syncthreads();
    }
    if (tid == 0) g_pcommit[blockIdx.x] = scr[0];

    // ---- last-block finalize ----
    __threadfence();
    if (tid == 0) {
        int tk = atomicAdd(&g_done, 1);
        flg = (tk == NBLOCKS - 1) ? 1 : 0;
    }
    __syncthreads();
    if (flg) {
        __threadfence();
        float v = 0.f;
        for (int i = tid; i < NBLOCKS; i += 256) v += g_pcommit[i];
        scr[tid] = v;
        __syncthreads();
        for (int s = 128; s > 0; s >>= 1) { if (tid < s) scr[tid] += scr[tid + s]; __syncthreads(); }
        float commitSum = scr[0];
        __syncthreads();

        v = 0.f;
        for (int i = tid; i < NBLOCKS; i += 256) v += g_pent[i];
        scr[tid] = v;
        __syncthreads();
        for (int s = 128; s > 0; s >>= 1) { if (tid < s) scr[tid] += scr[tid + s]; __syncthreads(); }
        float entSum = scr[0];
        __syncthreads();

        v = 0.f;
        for (int e = tid; e < 4096; e += 256) {
            float g = g_gram[e];
            v = fmaf(g, g, v);
        }
        scr[tid] = v;
        __syncthreads();
        for (int s = 128; s > 0; s >>= 1) { if (tid < s) scr[tid] += scr[tid + s]; __syncthreads(); }
        float orthoSum = scr[0];
        __syncthreads();

        v = 0.f;
        for (int i = tid; i < KCODES; i += 256) {
            float avg = (float)g_hist[i] / (float)N;
            v += avg * logf(avg + 1e-10f);
        }
        scr[tid] = v;
        __syncthreads();
        for (int s = 128; s > 0; s >>= 1) { if (tid < s) scr[tid] += scr[tid + s]; __syncthreads(); }
        float psum = scr[0];

        if (tid == 0) {
            size_t Q = (size_t)N * DDIM;
            float nu = g_usedp[0] + g_usedp[1] + g_usedp[2] + g_usedp[3];
            out[Q + 0] = commitSum / (float)Q;                 // commitment_loss
            out[Q + 1] = orthoSum / (nu * nu) - 1.f / nu;      // ortho_loss
            out[Q + 2] = entSum / ((float)N * 10.f);           // entropy_loss (/log2(1024))
            out[Q + 3] = expf(-psum);                          // perplexity
            out[Q + 4] = nu / (float)KCODES;                   // coverage
        }
    }
}

extern "C" void kernel_launch(void* const* d_in, const int* in_sizes, int n_in,
                              void* d_out, int out_size) {
    const float* x   = (const float*)d_in[0];   // [16,2048,64] fp32
    const float* emb = (const float*)d_in[1];   // [1024,64] fp32
    const float* cc  = (const float*)d_in[2];   // [1024] fp32
    int N = in_sizes[0] / DDIM;                 // 32768

    prep_kernel<<<4, 256>>>(emb, cc);
    ortho_kernel<<<16, 256>>>();
    main_kernel<<<NBLOCKS, 256>>>(x, emb, (float*)d_out, N);
}